// round 8
// baseline (speedup 1.0000x reference)
#include <cuda_runtime.h>
#include <cuda_fp16.h>
#include <cstdint>

#define NNODES 100000
#define NEDGES 1600000
#define NPAD   100096          // 782 * 128
#define NTILES 782
#define SCAN_B 256
#define NBLK ((NNODES + SCAN_B - 1) / SCAN_B)   // 391

// ---------------- static device scratch ----------------
__device__ float  g_f0[NPAD * 64], g_f1[NPAD * 64], g_f2[NPAD * 64];
__device__ __half g_f0s[NPAD * 64], g_f1s[NPAD * 64];
__device__ int    g_csrc[NEDGES];
__device__ int    g_deg[NNODES], g_rowptr[NNODES + 1], g_cursor[NNODES];
__device__ unsigned long long g_pstate[NBLK];   // decoupled-lookback state
__device__ float  g_dinv[NPAD];                 // tail stays zero
__device__ float  g_wfold[3 * 64 * 64];
__device__ int    g_flag;                       // 0 = int64 edges, 1 = int32

// ---------------- helpers ----------------
__device__ __forceinline__ uint32_t smem_u32(const void* p) {
    uint32_t a;
    asm("{ .reg .u64 t; cvta.to.shared.u64 t, %1; cvt.u32.u64 %0, t; }" : "=r"(a) : "l"(p));
    return a;
}
__device__ __forceinline__ uint32_t pack2h(float a, float b) {
    __half2 h = __floats2half2_rn(a, b);
    return *reinterpret_cast<uint32_t*>(&h);
}
__device__ __forceinline__ unsigned long long ldv64(const unsigned long long* p) {
    unsigned long long v;
    asm volatile("ld.volatile.global.u64 %0, [%1];" : "=l"(v) : "l"(p));
    return v;
}

#define LDSM4(d, a)                                                              \
    asm volatile("ldmatrix.sync.aligned.m8n8.x4.shared.b16 {%0,%1,%2,%3}, [%4];" \
                 : "=r"((d)[0]), "=r"((d)[1]), "=r"((d)[2]), "=r"((d)[3]) : "r"(a))
#define LDSM2(d, a)                                                              \
    asm volatile("ldmatrix.sync.aligned.m8n8.x2.shared.b16 {%0,%1}, [%2];"       \
                 : "=r"((d)[0]), "=r"((d)[1]) : "r"(a))
#define MMA(c, a, b)                                                             \
    asm volatile("mma.sync.aligned.m16n8k16.row.col.f32.f16.f16.f32 "            \
                 "{%0,%1,%2,%3},{%4,%5,%6,%7},{%8,%9},{%0,%1,%2,%3};"            \
                 : "+f"((c)[0]), "+f"((c)[1]), "+f"((c)[2]), "+f"((c)[3])        \
                 : "r"((a)[0]), "r"((a)[1]), "r"((a)[2]), "r"((a)[3]),           \
                   "r"((b)[0]), "r"((b)[1]))

// ---------------- prep kernels ----------------
__global__ void k_detect(const int* __restrict__ e32) {
    int nz = 0;
    for (int e = threadIdx.x; e < 2048; e += 256) nz |= e32[2 * e + 1];
    if (__syncthreads_or(nz) && threadIdx.x == 0) g_flag = 1;
}
__global__ void k_degree(const void* __restrict__ eptr) {
    int e = blockIdx.x * blockDim.x + threadIdx.x;
    if (e >= NEDGES) return;
    int d;
    if (g_flag == 0) d = (int)((const long long*)eptr)[NEDGES + e];
    else             d = ((const int*)eptr)[NEDGES + e];
    atomicAdd(&g_deg[d], 1);
}

// single-pass scan: block-local Hillis-Steele + decoupled lookback.
__global__ void k_scan_fused() {
    __shared__ int sh[SCAN_B];
    __shared__ int s_base;
    int b = blockIdx.x, t = threadIdx.x;
    int i = b * SCAN_B + t;
    int d = (i < NNODES) ? g_deg[i] : 0;
    sh[t] = d;
    __syncthreads();
    for (int off = 1; off < SCAN_B; off <<= 1) {
        int v = (t >= off) ? sh[t - off] : 0;
        __syncthreads();
        sh[t] += v;
        __syncthreads();
    }
    int incl = sh[t];
    int agg = sh[SCAN_B - 1];
    if (t == 0) {
        if (b == 0) {
            s_base = 0;
            atomicExch(&g_pstate[0], (2ull << 32) | (unsigned)agg);
        } else {
            atomicExch(&g_pstate[b], (1ull << 32) | (unsigned)agg);
        }
    }
    if (b > 0 && t < 32) {
        int running = 0;
        int j = b - 1;
        for (;;) {
            int jj = j - t;
            unsigned long long st;
            unsigned f;
            do {
                st = (jj >= 0) ? ldv64(&g_pstate[jj]) : (2ull << 32);
                f = (unsigned)(st >> 32);
            } while (__ballot_sync(0xffffffffu, f == 0));
            int v = (jj >= 0) ? (int)(st & 0xffffffffu) : 0;
            unsigned pm = __ballot_sync(0xffffffffu, (jj >= 0) && (f == 2));
            if (pm) {
                int fl = __ffs(pm) - 1;
                if ((int)t > fl) v = 0;
#pragma unroll
                for (int o = 16; o; o >>= 1) v += __shfl_xor_sync(0xffffffffu, v, o);
                running += v;
                break;
            }
#pragma unroll
            for (int o = 16; o; o >>= 1) v += __shfl_xor_sync(0xffffffffu, v, o);
            running += v;
            j -= 32;
        }
        if (t == 0) {
            s_base = running;
            atomicExch(&g_pstate[b], (2ull << 32) | (unsigned)(running + agg));
        }
    }
    __syncthreads();
    int base = s_base;
    if (i < NNODES) {
        int r = base + incl - d;
        g_rowptr[i] = r;
        g_cursor[i] = r;
        g_dinv[i] = rsqrtf((float)(d > 0 ? d : 1));
        if (i == NNODES - 1) g_rowptr[NNODES] = base + incl;
    }
}

__global__ void k_fill(const void* __restrict__ eptr) {
    int e = blockIdx.x * blockDim.x + threadIdx.x;
    if (e >= NEDGES) return;
    int s, d;
    if (g_flag == 0) {
        const long long* p = (const long long*)eptr;
        s = (int)p[e]; d = (int)p[NEDGES + e];
    } else {
        const int* p = (const int*)eptr;
        s = p[e]; d = p[NEDGES + e];
    }
    int pos = atomicAdd(&g_cursor[d], 1);
    g_csrc[pos] = s;
}
// fold thetas: t0=[3,-3,0.75], t1=[0,3,-1.5], t2=[0,0,0.75]
__global__ void k_fold(const float* __restrict__ Wm1) {
    int idx = blockIdx.x * blockDim.x + threadIdx.x;
    if (idx >= 3 * 64 * 64) return;
    int k = idx >> 12, ij = idx & 4095;
    float c0, c1, c2;
    if (k == 0)      { c0 = 3.0f;  c1 = 0.0f;  c2 = 0.0f;  }
    else if (k == 1) { c0 = -3.0f; c1 = 3.0f;  c2 = 0.0f;  }
    else             { c0 = 0.75f; c1 = -1.5f; c2 = 0.75f; }
    g_wfold[idx] = c0 * Wm1[ij] + c1 * Wm1[4096 + ij] + c2 * Wm1[2 * 4096 + ij];
}
// f0s = f0 * dinv (rowwise), fp16
__global__ void k_scale(const float* __restrict__ f, __half* __restrict__ fs) {
    int idx = blockIdx.x * blockDim.x + threadIdx.x;
    int row = idx >> 5;
    int c2 = idx & 31;
    float dn = g_dinv[row];
    float2 v = *(const float2*)&f[(size_t)row * 64 + c2 * 2];
    *(uint32_t*)&fs[(size_t)row * 64 + c2 * 2] = pack2h(v.x * dn, v.y * dn);
}

// ---------------- smem layout for MMA kernels ----------------
#define LDH 72
#define LDF 68
#define OFF_BIAS 0
#define OFF_WM2  512
#define OFF_CT   1024
#define OFF_AH   1024
#define OFF_AL   (OFF_AH + 128 * LDH * 2)
#define OFF_WH   (OFF_AL + 128 * LDH * 2)
#define OFF_WL   (OFF_WH + 64 * LDH * 2)
#define SMEM_SZ  (OFF_WL + 64 * LDH * 2)

// common mma inner loop (A/W already staged)
#define MMA_LOOP(accv)                                                           \
    _Pragma("unroll")                                                            \
    for (int kc = 0; kc < 64; kc += 16) {                                        \
        uint32_t ah[2][4], al[2][4];                                             \
        _Pragma("unroll")                                                        \
        for (int mi = 0; mi < 2; mi++) {                                         \
            uint32_t aa = sb + OFF_AH + ((arow + mi * 16) * LDH + kc + acol) * 2;\
            LDSM4(ah[mi], aa);                                                   \
            LDSM4(al[mi], aa + (OFF_AL - OFF_AH));                               \
        }                                                                        \
        _Pragma("unroll")                                                        \
        for (int ni = 0; ni < 4; ni++) {                                         \
            uint32_t wh[2], wl[2];                                               \
            uint32_t ba = sb + OFF_WH + ((brow + ni * 8) * LDH + kc + bcol) * 2; \
            LDSM2(wh, ba);                                                       \
            LDSM2(wl, ba + (OFF_WL - OFF_WH));                                   \
            _Pragma("unroll")                                                    \
            for (int mi = 0; mi < 2; mi++) {                                     \
                MMA(accv[mi][ni], ah[mi], wh);                                   \
                MMA(accv[mi][ni], al[mi], wh);                                   \
                MMA(accv[mi][ni], ah[mi], wl);                                   \
            }                                                                    \
        }                                                                        \
    }

#define STAGE_A(pa, lda)                                                         \
    _Pragma("unroll")                                                            \
    for (int it = 0; it < 4; it++) {                                             \
        int idx = tid + it * 256;                                                \
        int row = idx >> 3;                                                      \
        int c8 = (idx & 7) * 8;                                                  \
        int grow = row0 + row;                                                   \
        if (grow >= NNODES) grow = NNODES - 1;                                   \
        const float* gp = (pa) + (size_t)grow * (lda) + c8;                      \
        float4 u0 = *(const float4*)gp;                                          \
        float4 u1 = *(const float4*)(gp + 4);                                    \
        float fv[8] = {u0.x, u0.y, u0.z, u0.w, u1.x, u1.y, u1.z, u1.w};          \
        float lo[8];                                                             \
        _Pragma("unroll")                                                        \
        for (int j = 0; j < 8; j++) {                                            \
            __half h = __float2half_rn(fv[j]);                                   \
            lo[j] = fv[j] - __half2float(h);                                     \
        }                                                                        \
        uint4 vh, vl;                                                            \
        vh.x = pack2h(fv[0], fv[1]); vh.y = pack2h(fv[2], fv[3]);                \
        vh.z = pack2h(fv[4], fv[5]); vh.w = pack2h(fv[6], fv[7]);                \
        vl.x = pack2h(lo[0], lo[1]); vl.y = pack2h(lo[2], lo[3]);                \
        vl.z = pack2h(lo[4], lo[5]); vl.w = pack2h(lo[6], lo[7]);                \
        *(uint4*)&sAh[row * LDH + c8] = vh;                                      \
        *(uint4*)&sAl[row * LDH + c8] = vl;                                      \
    }

#define STAGE_W(Wc)                                                              \
    for (int i = tid; i < 4096; i += 256) {                                      \
        int k = i >> 6, n = i & 63;                                              \
        float w = (Wc)[i];                                                       \
        __half hh = __float2half_rn(w);                                          \
        sWh[n * LDH + k] = hh;                                                   \
        sWl[n * LDH + k] = __float2half_rn(w - __half2float(hh));                \
    }

// ---------------- fused 2-layer MLP: f0 = relu(relu(x@W1+b1)@W2+b2) ----------------
__global__ void __launch_bounds__(256) k_mlp(
    const float* __restrict__ x,
    const float* __restrict__ W1, const float* __restrict__ b1,
    const float* __restrict__ W2, const float* __restrict__ b2,
    float* __restrict__ f0)
{
    extern __shared__ char smem[];
    uint32_t sb = smem_u32(smem);
    float* sbias = (float*)(smem + OFF_BIAS);   // [0..63]=b1, [64..127]=b2
    __half* sAh = (__half*)(smem + OFF_AH);
    __half* sAl = (__half*)(smem + OFF_AL);
    __half* sWh = (__half*)(smem + OFF_WH);
    __half* sWl = (__half*)(smem + OFF_WL);

    int tid = threadIdx.x;
    int warp = tid >> 5, lane = tid & 31;
    int wy = warp & 3, wx = warp >> 2;
    int row0 = blockIdx.x * 128;

    if (tid < 64) sbias[tid] = b1[tid];
    else if (tid < 128) sbias[tid] = b2[tid - 64];

    float acc[2][4][4];
#pragma unroll
    for (int mi = 0; mi < 2; mi++)
#pragma unroll
        for (int ni = 0; ni < 4; ni++)
#pragma unroll
            for (int j = 0; j < 4; j++) acc[mi][ni][j] = 0.f;

    const int arow = wy * 32 + (lane & 7) + ((lane >> 3) & 1) * 8;
    const int acol = ((lane >> 4) & 1) * 8;
    const int brow = wx * 32 + (lane & 7);
    const int bcol = ((lane >> 3) & 1) * 8;

    // ---- layer 1 (K=128: two segments of x) ----
    const float* Aseg[2] = {x, x + 64};
#pragma unroll
    for (int sg = 0; sg < 2; sg++) {
        __syncthreads();
        STAGE_A(Aseg[sg], 128);
        STAGE_W(W1 + sg * 4096);
        __syncthreads();
        MMA_LOOP(acc);
    }

    __syncthreads();   // all reads of staged A/W complete
    // ---- convert h1 fragments -> sAh/sAl (A for layer 2), reset acc ----
    {
        int gq = lane >> 2, qp = (lane & 3) * 2;
#pragma unroll
        for (int mi = 0; mi < 2; mi++)
#pragma unroll
            for (int ni = 0; ni < 4; ni++) {
                int r = wy * 32 + mi * 16 + gq;
                int c = wx * 32 + ni * 8 + qp;
                float v00 = fmaxf(acc[mi][ni][0] + sbias[c], 0.f);
                float v01 = fmaxf(acc[mi][ni][1] + sbias[c + 1], 0.f);
                float v10 = fmaxf(acc[mi][ni][2] + sbias[c], 0.f);
                float v11 = fmaxf(acc[mi][ni][3] + sbias[c + 1], 0.f);
                __half h;
                h = __float2half_rn(v00);
                sAh[r * LDH + c] = h;           sAl[r * LDH + c] = __float2half_rn(v00 - __half2float(h));
                h = __float2half_rn(v01);
                sAh[r * LDH + c + 1] = h;       sAl[r * LDH + c + 1] = __float2half_rn(v01 - __half2float(h));
                h = __float2half_rn(v10);
                sAh[(r + 8) * LDH + c] = h;     sAl[(r + 8) * LDH + c] = __float2half_rn(v10 - __half2float(h));
                h = __float2half_rn(v11);
                sAh[(r + 8) * LDH + c + 1] = h; sAl[(r + 8) * LDH + c + 1] = __float2half_rn(v11 - __half2float(h));
                acc[mi][ni][0] = 0.f; acc[mi][ni][1] = 0.f;
                acc[mi][ni][2] = 0.f; acc[mi][ni][3] = 0.f;
            }
    }
    STAGE_W(W2);
    __syncthreads();

    // ---- layer 2 ----
    MMA_LOOP(acc);

    // ---- epilogue: park, add b2 + relu, write f0 ----
    __syncthreads();
    float* sC = (float*)(smem + OFF_CT);
    {
        int gq = lane >> 2, qp = (lane & 3) * 2;
#pragma unroll
        for (int mi = 0; mi < 2; mi++)
#pragma unroll
            for (int ni = 0; ni < 4; ni++) {
                int r = wy * 32 + mi * 16 + gq;
                int c = wx * 32 + ni * 8 + qp;
                *(float2*)&sC[r * LDF + c]       = make_float2(acc[mi][ni][0], acc[mi][ni][1]);
                *(float2*)&sC[(r + 8) * LDF + c] = make_float2(acc[mi][ni][2], acc[mi][ni][3]);
            }
    }
    __syncthreads();
#pragma unroll
    for (int it = 0; it < 4; it++) {
        int idx = tid + it * 256;
        int row = idx >> 3;
        int c8 = (idx & 7) * 8;
        float v[8];
#pragma unroll
        for (int j = 0; j < 8; j++)
            v[j] = fmaxf(sC[row * LDF + c8 + j] + sbias[64 + c8 + j], 0.f);
        size_t base = (size_t)(row0 + row) * 64 + c8;
        *(float4*)(f0 + base)     = make_float4(v[0], v[1], v[2], v[3]);
        *(float4*)(f0 + base + 4) = make_float4(v[4], v[5], v[6], v[7]);
    }
}

// ---------------- head: out = relu(f0@Wf0 + f1@Wf1 + f2@Wf2 + bm1) @ Wm2 + bm2 ----------------
__global__ void __launch_bounds__(256) k_head(
    const float* __restrict__ A0, const float* __restrict__ A1, const float* __restrict__ A2,
    const float* __restrict__ W, const float* __restrict__ bias,
    const float* __restrict__ Wm2, const float* __restrict__ bm2,
    float* __restrict__ out)
{
    extern __shared__ char smem[];
    uint32_t sb = smem_u32(smem);
    float* sbias = (float*)(smem + OFF_BIAS);
    float* swm2  = (float*)(smem + OFF_WM2);
    __half* sAh = (__half*)(smem + OFF_AH);
    __half* sAl = (__half*)(smem + OFF_AL);
    __half* sWh = (__half*)(smem + OFF_WH);
    __half* sWl = (__half*)(smem + OFF_WL);

    int tid = threadIdx.x;
    int warp = tid >> 5, lane = tid & 31;
    int wy = warp & 3, wx = warp >> 2;
    int row0 = blockIdx.x * 128;

    if (tid < 64) sbias[tid] = bias[tid];
    if (tid < 128) swm2[tid] = Wm2[tid];

    float acc[2][4][4];
#pragma unroll
    for (int mi = 0; mi < 2; mi++)
#pragma unroll
        for (int ni = 0; ni < 4; ni++)
#pragma unroll
            for (int j = 0; j < 4; j++) acc[mi][ni][j] = 0.f;

    const float* Aseg[3] = {A0, A1, A2};
    const int arow = wy * 32 + (lane & 7) + ((lane >> 3) & 1) * 8;
    const int acol = ((lane >> 4) & 1) * 8;
    const int brow = wx * 32 + (lane & 7);
    const int bcol = ((lane >> 3) & 1) * 8;

#pragma unroll
    for (int sg = 0; sg < 3; sg++) {
        __syncthreads();
        STAGE_A(Aseg[sg], 64);
        STAGE_W(W + sg * 4096);
        __syncthreads();
        MMA_LOOP(acc);
    }

    __syncthreads();
    float* sC = (float*)(smem + OFF_CT);
    {
        int gq = lane >> 2, qp = (lane & 3) * 2;
#pragma unroll
        for (int mi = 0; mi < 2; mi++)
#pragma unroll
            for (int ni = 0; ni < 4; ni++) {
                int r = wy * 32 + mi * 16 + gq;
                int c = wx * 32 + ni * 8 + qp;
                *(float2*)&sC[r * LDF + c]       = make_float2(acc[mi][ni][0], acc[mi][ni][1]);
                *(float2*)&sC[(r + 8) * LDF + c] = make_float2(acc[mi][ni][2], acc[mi][ni][3]);
            }
    }
    __syncthreads();
    int r = tid >> 1, c2 = tid & 1;
    float s = 0.f;
#pragma unroll
    for (int c = 0; c < 64; c++)
        s = fmaf(fmaxf(sC[r * LDF + c] + sbias[c], 0.f), swm2[c * 2 + c2], s);
    if (row0 + r < NNODES)
        out[(size_t)(row0 + r) * 2 + c2] = s + __ldg(&bm2[c2]);
}

// ---------------- propagation: 8 lanes x 16B per source row, 4 rows in flight ----------------
template <bool OUT_SCALED>
__global__ void __launch_bounds__(256) k_prop(
    const float* __restrict__ fin, const __half* __restrict__ fins,
    float* __restrict__ fout, __half* __restrict__ fouts)
{
    int n = (blockIdx.x * blockDim.x + threadIdx.x) >> 5;
    int lane = threadIdx.x & 31;
    int g = lane >> 3, l8 = lane & 7;
    int start = g_rowptr[n], end = g_rowptr[n + 1];

    float fa[8] = {0, 0, 0, 0, 0, 0, 0, 0};
    float fb[8] = {0, 0, 0, 0, 0, 0, 0, 0};

    for (int i = start; i < end; i += 32) {
        int s = 0;
        if (i + lane < end) s = g_csrc[i + lane];
#pragma unroll
        for (int j = 0; j < 32; j += 8) {
            int sj0 = __shfl_sync(0xffffffffu, s, j + g);
            int sj1 = __shfl_sync(0xffffffffu, s, j + 4 + g);
            bool a0 = (i + j + g) < end;
            bool a1 = (i + j + 4 + g) < end;
            if (a0) {
                uint4 v = *(const uint4*)&fins[(size_t)sj0 * 64 + l8 * 8];
                float2 p0 = __half22float2(*(__half2*)&v.x);
                float2 p1 = __half22float2(*(__half2*)&v.y);
                float2 p2 = __half22float2(*(__half2*)&v.z);
                float2 p3 = __half22float2(*(__half2*)&v.w);
                fa[0] += p0.x; fa[1] += p0.y; fa[2] += p1.x; fa[3] += p1.y;
                fa[4] += p2.x; fa[5] += p2.y; fa[6] += p3.x; fa[7] += p3.y;
            }
            if (a1) {
                uint4 v = *(const uint4*)&fins[(size_t)sj1 * 64 + l8 * 8];
                float2 p0 = __half22float2(*(__half2*)&v.x);
                float2 p1 = __half22float2(*(__half2*)&v.y);
                float2 p2 = __half22float2(*(__half2*)&v.z);
                float2 p3 = __half22float2(*(__half2*)&v.w);
                fb[0] += p0.x; fb[1] += p0.y; fb[2] += p1.x; fb[3] += p1.y;
                fb[4] += p2.x; fb[5] += p2.y; fb[6] += p3.x; fb[7] += p3.y;
            }
        }
    }
#pragma unroll
    for (int k = 0; k < 8; k++) {
        float v = fa[k] + fb[k];
        v += __shfl_xor_sync(0xffffffffu, v, 8);
        v += __shfl_xor_sync(0xffffffffu, v, 16);
        fa[k] = v;
    }
    if (g == 0) {
        float dn = g_dinv[n];
        size_t base = (size_t)n * 64 + l8 * 8;
        float4 c0 = *(const float4*)&fin[base];
        float4 c1 = *(const float4*)&fin[base + 4];
        float o[8];
        o[0] = c0.x - fa[0] * dn; o[1] = c0.y - fa[1] * dn;
        o[2] = c0.z - fa[2] * dn; o[3] = c0.w - fa[3] * dn;
        o[4] = c1.x - fa[4] * dn; o[5] = c1.y - fa[5] * dn;
        o[6] = c1.z - fa[6] * dn; o[7] = c1.w - fa[7] * dn;
        *(float4*)&fout[base]     = make_float4(o[0], o[1], o[2], o[3]);
        *(float4*)&fout[base + 4] = make_float4(o[4], o[5], o[6], o[7]);
        if (OUT_SCALED) {
            uint4 ps;
            ps.x = pack2h(o[0] * dn, o[1] * dn); ps.y = pack2h(o[2] * dn, o[3] * dn);
            ps.z = pack2h(o[4] * dn, o[5] * dn); ps.w = pack2h(o[6] * dn, o[7] * dn);
            *(uint4*)&fouts[base] = ps;
        }
    }
}

// ---------------- launch ----------------
extern "C" void kernel_launch(void* const* d_in, const int* in_sizes, int n_in,
                              void* d_out, int out_size)
{
    const float* x   = (const float*)d_in[0];
    const void*  ei  = d_in[1];
    const float* W1  = (const float*)d_in[2];
    const float* b1  = (const float*)d_in[3];
    const float* W2  = (const float*)d_in[4];
    const float* b2  = (const float*)d_in[5];
    const float* Wm1 = (const float*)d_in[6];
    const float* bm1 = (const float*)d_in[7];
    const float* Wm2 = (const float*)d_in[8];
    const float* bm2 = (const float*)d_in[9];
    float* out = (float*)d_out;

    float *f0, *f1, *f2, *pwf;
    __half *f0s, *f1s;
    int *pdeg, *pflag;
    unsigned long long* pstate;
    cudaGetSymbolAddress((void**)&f0, g_f0);
    cudaGetSymbolAddress((void**)&f1, g_f1);
    cudaGetSymbolAddress((void**)&f2, g_f2);
    cudaGetSymbolAddress((void**)&f0s, g_f0s);
    cudaGetSymbolAddress((void**)&f1s, g_f1s);
    cudaGetSymbolAddress((void**)&pwf, g_wfold);
    cudaGetSymbolAddress((void**)&pdeg, g_deg);
    cudaGetSymbolAddress((void**)&pflag, g_flag);
    cudaGetSymbolAddress((void**)&pstate, g_pstate);

    cudaFuncSetAttribute(k_mlp, cudaFuncAttributeMaxDynamicSharedMemorySize, SMEM_SZ);
    cudaFuncSetAttribute(k_head, cudaFuncAttributeMaxDynamicSharedMemorySize, SMEM_SZ);

    static cudaStream_t s_side = [] {
        cudaStream_t s;
        return (cudaStreamCreateWithFlags(&s, cudaStreamNonBlocking) == cudaSuccess)
                   ? s : (cudaStream_t)nullptr;
    }();
    static cudaEvent_t e_fork = [] {
        cudaEvent_t e;
        return (cudaEventCreateWithFlags(&e, cudaEventDisableTiming) == cudaSuccess)
                   ? e : (cudaEvent_t)nullptr;
    }();
    static cudaEvent_t e_dinv = [] {
        cudaEvent_t e;
        return (cudaEventCreateWithFlags(&e, cudaEventDisableTiming) == cudaSuccess)
                   ? e : (cudaEvent_t)nullptr;
    }();
    static cudaEvent_t e_join = [] {
        cudaEvent_t e;
        return (cudaEventCreateWithFlags(&e, cudaEventDisableTiming) == cudaSuccess)
                   ? e : (cudaEvent_t)nullptr;
    }();

    bool overlap = s_side && e_fork && e_dinv && e_join;
    cudaStream_t sp = overlap ? s_side : (cudaStream_t)0;

    if (overlap) {
        cudaEventRecord(e_fork, 0);
        cudaStreamWaitEvent(s_side, e_fork, 0);
    }

    // ---- side chain ----
    k_fold<<<(3 * 64 * 64 + 255) / 256, 256, 0, sp>>>(Wm1);
    cudaMemsetAsync(pdeg, 0, NNODES * sizeof(int), sp);
    cudaMemsetAsync(pflag, 0, sizeof(int), sp);
    cudaMemsetAsync(pstate, 0, NBLK * sizeof(unsigned long long), sp);
    k_detect<<<1, 256, 0, sp>>>((const int*)ei);
    k_degree<<<NEDGES / 256, 256, 0, sp>>>(ei);
    k_scan_fused<<<NBLK, SCAN_B, 0, sp>>>();
    if (overlap) cudaEventRecord(e_dinv, s_side);
    k_fill<<<NEDGES / 256, 256, 0, sp>>>(ei);
    if (overlap) cudaEventRecord(e_join, s_side);

    // ---- main chain ----
    k_mlp<<<NTILES, 256, SMEM_SZ>>>(x, W1, b1, W2, b2, f0);
    if (overlap) cudaStreamWaitEvent(0, e_dinv, 0);
    k_scale<<<(NNODES * 32) / 256, 256>>>(f0, f0s);
    if (overlap) cudaStreamWaitEvent(0, e_join, 0);

    k_prop<true><<<(NNODES * 32) / 256, 256>>>(f0, f0s, f1, f1s);
    k_prop<false><<<(NNODES * 32) / 256, 256>>>(f1, f1s, f2, nullptr);

    k_head<<<NTILES, 256, SMEM_SZ>>>(f0, f1, f2, pwf, bm1, Wm2, bm2, out);
}